// round 2
// baseline (speedup 1.0000x reference)
#include <cuda_runtime.h>
#include <math.h>

// ---------------- problem constants ----------------
#define B_   64
#define C_   256
#define HW_  4096            // 64*64
#define TILE 64              // spatial positions per block in pass1
#define NTILES (HW_ / TILE)  // 64
#define PLANES 128
#define HIDDEN 16
#define K_   8
#define ATT_CH 4
#define EPS_ 1e-5f

// ---------------- device scratch (zero-init at module load; finalize re-zeros) ----------------
__device__ float g_sumc[B_ * C_];   // per (b,c): sum over s of x           -> beta_c (and suma)
__device__ float g_num [B_ * C_];   // per (b,c): sum over s of x*exp(l_s)  -> context numerator
__device__ float g_D   [B_];        // per b: sum over s of exp(l_s)
__device__ float g_summ[B_];        // per b: sum over s of max_c x

// ---------------- dynamic smem layout for pass1 (floats) ----------------
#define OFF_SX  0                       // [C_][TILE]  = 16384 f (64 KB)
#define OFF_SW  (C_ * TILE)             // [C_]        =   256 f
#define OFF_AL  (OFF_SW + C_)           // [16][TILE]  =  1024 f
#define OFF_AM  (OFF_AL + 16 * TILE)    // [16][TILE]  =  1024 f
#define OFF_SE  (OFF_AM + 16 * TILE)    // [TILE]      =    64 f
#define OFF_RED (OFF_SE + TILE)         // [8]
#define SMEM_FLOATS (OFF_RED + 8)
#define SMEM_BYTES  (SMEM_FLOATS * 4)   // 75040 B -> 3 CTAs/SM

// ---------------- kernel 1: single streaming pass over x ----------------
__global__ __launch_bounds__(256) void pass1(const float* __restrict__ x,
                                             const float* __restrict__ w_mask,
                                             const float* __restrict__ b_mask) {
    extern __shared__ float sm[];
    float* sx    = sm + OFF_SX;     // row stride TILE(=64) floats
    float* sw    = sm + OFF_SW;
    float* aux_l = sm + OFF_AL;
    float* aux_m = sm + OFF_AM;
    float* se    = sm + OFF_SE;
    float* red   = sm + OFF_RED;

    const int t    = threadIdx.x;    // 0..255
    const int w    = t >> 5;         // warp 0..7
    const int lane = t & 31;
    const int b    = blockIdx.y;
    const int tile = blockIdx.x;

    sw[t] = w_mask[t];

    // ---- coalesced tile load: 16 iters, each warp covers 2 rows (lanes 0-15 / 16-31) ----
    const float4* xb = reinterpret_cast<const float4*>(x)
                     + (size_t)b * C_ * (HW_ / 4) + (size_t)tile * (TILE / 4);
    #pragma unroll 4
    for (int it = 0; it < 16; ++it) {
        int c = it * 16 + w * 2 + (lane >> 4);
        int i = lane & 15;
        float4 v = xb[(size_t)c * (HW_ / 4) + i];
        *reinterpret_cast<float4*>(&sx[c * TILE + i * 4]) = v;
    }
    __syncthreads();

    // ---- phase 2: per-position logit & channel-max, vectorized float4 ----
    // thread: group g = t>>4 (16 channels), position-quad p = t&15
    {
        const int g = t >> 4;
        const int p = t & 15;
        float4 lp = make_float4(0.f, 0.f, 0.f, 0.f);
        float4 mp = make_float4(-1e30f, -1e30f, -1e30f, -1e30f);
        #pragma unroll
        for (int cc = 0; cc < 16; ++cc) {
            int c = g * 16 + cc;
            float wc = sw[c];                                    // broadcast LDS
            float4 v = *reinterpret_cast<const float4*>(&sx[c * TILE + p * 4]);
            lp.x = fmaf(v.x, wc, lp.x); lp.y = fmaf(v.y, wc, lp.y);
            lp.z = fmaf(v.z, wc, lp.z); lp.w = fmaf(v.w, wc, lp.w);
            mp.x = fmaxf(mp.x, v.x);    mp.y = fmaxf(mp.y, v.y);
            mp.z = fmaxf(mp.z, v.z);    mp.w = fmaxf(mp.w, v.w);
        }
        *reinterpret_cast<float4*>(&aux_l[g * TILE + p * 4]) = lp;
        *reinterpret_cast<float4*>(&aux_m[g * TILE + p * 4]) = mp;
    }
    __syncthreads();

    // ---- combine partials: threads 0..63 own one position each ----
    if (t < TILE) {
        float l = b_mask[0];
        float m = -1e30f;
        #pragma unroll
        for (int g2 = 0; g2 < 16; ++g2) {
            l += aux_l[g2 * TILE + t];
            m  = fmaxf(m, aux_m[g2 * TILE + t]);
        }
        float e = __expf(l);            // unnormalized softmax weight (logits O(3))
        se[t] = e;
        #pragma unroll
        for (int off = 16; off > 0; off >>= 1) {
            e += __shfl_down_sync(0xffffffffu, e, off);
            m += __shfl_down_sync(0xffffffffu, m, off);
        }
        if (lane == 0) { red[(t >> 5) * 2] = e; red[(t >> 5) * 2 + 1] = m; }
    }
    __syncthreads();
    if (t == 0) {
        atomicAdd(&g_D[b],    red[0] + red[2]);
        atomicAdd(&g_summ[b], red[1] + red[3]);
    }

    // ---- phase 3: per-channel sums, vectorized float4 with quad rotation ----
    {
        const int c = t;
        const int rot = c & 15;
        float4 sv  = make_float4(0.f, 0.f, 0.f, 0.f);
        float4 sve = make_float4(0.f, 0.f, 0.f, 0.f);
        #pragma unroll
        for (int q = 0; q < 16; ++q) {
            int jj = (q + rot) & 15;
            float4 v = *reinterpret_cast<const float4*>(&sx[c * TILE + jj * 4]);
            float4 e = *reinterpret_cast<const float4*>(&se[jj * 4]);
            sv.x += v.x; sv.y += v.y; sv.z += v.z; sv.w += v.w;
            sve.x = fmaf(v.x, e.x, sve.x); sve.y = fmaf(v.y, e.y, sve.y);
            sve.z = fmaf(v.z, e.z, sve.z); sve.w = fmaf(v.w, e.w, sve.w);
        }
        float svs  = (sv.x + sv.y) + (sv.z + sv.w);
        float sves = (sve.x + sve.y) + (sve.z + sve.w);
        atomicAdd(&g_sumc[b * C_ + c], svs);
        atomicAdd(&g_num [b * C_ + c], sves);
    }
}

// ---------------- kernel 2: per-batch finalizer (also re-zeros scratch) ----------------
__global__ __launch_bounds__(256) void finalize(
        const float* __restrict__ w_cm1, const float* __restrict__ b_cm1,
        const float* __restrict__ ln_w,  const float* __restrict__ ln_b,
        const float* __restrict__ w_cm2, const float* __restrict__ b_cm2,
        const float* __restrict__ w_net1, const float* __restrict__ w_net2,
        const float* __restrict__ w_fc,
        const float* __restrict__ bn_w,  const float* __restrict__ bn_b,
        const float* __restrict__ bn_mean, const float* __restrict__ bn_var,
        const float* __restrict__ w_kfc,
        float* __restrict__ out) {
    __shared__ float ctx[C_], bc[C_], tg[PLANES], sout[C_];
    __shared__ float red_s[4], red_q[4], red_a[8];
    __shared__ float hid[HIDDEN], o8[K_], kar[ATT_CH], fv[K_];
    __shared__ float sh_mval;

    const int t = threadIdx.x;       // 0..255
    const int b = blockIdx.x;
    const int lane = t & 31, wp = t >> 5;

    const float invD = 1.f / g_D[b];
    const float mval = g_summ[b] * (1.f / (float)HW_);
    if (t == 0) sh_mval = mval;

    ctx[t] = g_num [b * C_ + t] * invD;
    bc[t]  = g_sumc[b * C_ + t] * (1.f / (float)HW_);

    // reduce bc -> aval = mean over channels of bc (== suma/(C*HW))
    {
        float s = bc[t];
        #pragma unroll
        for (int off = 16; off > 0; off >>= 1) s += __shfl_down_sync(0xffffffffu, s, off);
        if (lane == 0) red_a[wp] = s;
    }
    __syncthreads();

    // re-zero scratch for the next graph replay (all reads of g_* are done)
    g_num [b * C_ + t] = 0.f;
    g_sumc[b * C_ + t] = 0.f;
    if (t == 0) { g_D[b] = 0.f; g_summ[b] = 0.f; }

    const float aval = (red_a[0] + red_a[1] + red_a[2] + red_a[3] +
                        red_a[4] + red_a[5] + red_a[6] + red_a[7]) * (1.f / (float)C_);
    const float mv = sh_mval;

    // context_modeling conv1: t < 128 planes, dot over 256 channels
    float tv = 0.f;
    if (t < PLANES) {
        float acc = b_cm1[t];
        const float* wr = w_cm1 + t * C_;
        #pragma unroll 8
        for (int c = 0; c < C_; ++c) acc = fmaf(ctx[c], wr[c], acc);
        tv = acc;
    }
    // LayerNorm over 128 values
    float s1 = tv, s2 = tv * tv;
    #pragma unroll
    for (int off = 16; off > 0; off >>= 1) {
        s1 += __shfl_down_sync(0xffffffffu, s1, off);
        s2 += __shfl_down_sync(0xffffffffu, s2, off);
    }
    if (t < PLANES && lane == 0) { red_s[wp] = s1; red_q[wp] = s2; }
    __syncthreads();
    if (t < PLANES) {
        float S  = red_s[0] + red_s[1] + red_s[2] + red_s[3];
        float SQ = red_q[0] + red_q[1] + red_q[2] + red_q[3];
        float mu  = S * (1.f / PLANES);
        float var = SQ * (1.f / PLANES) - mu * mu;
        float tn = (tv - mu) * rsqrtf(var + EPS_) * ln_w[t] + ln_b[t];
        tg[t] = 0.5f * tn * (1.f + erff(tn * 0.70710678118654752f));   // exact GELU
    }
    __syncthreads();

    // conv2 + assemble out = beta_c + beta_g + beta_s
    {
        float acc = b_cm2[t];
        const float* wr = w_cm2 + t * PLANES;
        #pragma unroll 8
        for (int p = 0; p < PLANES; ++p) acc = fmaf(tg[p], wr[p], acc);
        sout[t] = bc[t] + acc + ((t & 1) ? mv : aval);
    }
    __syncthreads();

    if (t < HIDDEN) {
        float h = 0.f;
        const float* wr = w_net1 + t * C_;
        #pragma unroll 8
        for (int c = 0; c < C_; ++c) h = fmaf(sout[c], wr[c], h);
        hid[t] = fmaxf(h, 0.f);
    }
    __syncthreads();
    if (t < K_) {
        float o = 0.f;
        #pragma unroll
        for (int q = 0; q < HIDDEN; ++q) o = fmaf(hid[q], w_net2[t * HIDDEN + q], o);
        o8[t] = o;
    }
    __syncthreads();
    if (t < ATT_CH) {
        float ka = 0.f;
        #pragma unroll
        for (int k = 0; k < K_; ++k) ka = fmaf(o8[k], w_fc[t * K_ + k], ka);
        ka = (ka - bn_mean[t]) * rsqrtf(bn_var[t] + EPS_) * bn_w[t] + bn_b[t];
        kar[t] = fmaxf(ka, 0.f);
    }
    __syncthreads();
    if (t < K_) {
        float kk = 0.f;
        #pragma unroll
        for (int q = 0; q < ATT_CH; ++q) kk = fmaf(kar[q], w_kfc[t * ATT_CH + q], kk);
        float ker = 1.f / (1.f + __expf(-kk));
        fv[t] = o8[t] * ker * (1.f / 30.f);
    }
    __syncthreads();
    if (t == 0) {
        float mx = -1e30f;
        #pragma unroll
        for (int k = 0; k < K_; ++k) mx = fmaxf(mx, fv[k]);
        float e[K_], s = 0.f;
        #pragma unroll
        for (int k = 0; k < K_; ++k) { e[k] = __expf(fv[k] - mx); s += e[k]; }
        float inv = 1.f / s;
        #pragma unroll
        for (int k = 0; k < K_; ++k) out[b * K_ + k] = e[k] * inv;
    }
}

// ---------------- launch ----------------
extern "C" void kernel_launch(void* const* d_in, const int* in_sizes, int n_in,
                              void* d_out, int out_size) {
    const float* x      = (const float*)d_in[0];
    const float* w_mask = (const float*)d_in[1];
    const float* b_mask = (const float*)d_in[2];
    const float* w_cm1  = (const float*)d_in[3];
    const float* b_cm1  = (const float*)d_in[4];
    const float* ln_w   = (const float*)d_in[5];
    const float* ln_b   = (const float*)d_in[6];
    const float* w_cm2  = (const float*)d_in[7];
    const float* b_cm2  = (const float*)d_in[8];
    const float* w_net1 = (const float*)d_in[9];
    const float* w_net2 = (const float*)d_in[10];
    const float* w_fc   = (const float*)d_in[11];
    const float* bn_w   = (const float*)d_in[12];
    const float* bn_b   = (const float*)d_in[13];
    const float* bn_mean= (const float*)d_in[14];
    const float* bn_var = (const float*)d_in[15];
    const float* w_kfc  = (const float*)d_in[16];
    float* out = (float*)d_out;

    cudaFuncSetAttribute(pass1, cudaFuncAttributeMaxDynamicSharedMemorySize, SMEM_BYTES);
    pass1<<<dim3(NTILES, B_), 256, SMEM_BYTES>>>(x, w_mask, b_mask);
    finalize<<<B_, 256>>>(w_cm1, b_cm1, ln_w, ln_b, w_cm2, b_cm2,
                          w_net1, w_net2, w_fc, bn_w, bn_b, bn_mean, bn_var,
                          w_kfc, out);
}

// round 3
// speedup vs baseline: 1.3199x; 1.3199x over previous
#include <cuda_runtime.h>
#include <math.h>

// ---------------- problem constants ----------------
#define B_   64
#define C_   256
#define HW_  4096            // 64*64
#define TILE 32              // spatial positions per tile
#define SUBT 4               // tiles per CTA
#define NBLK (HW_ / (TILE * SUBT))   // 32
#define PLANES 128
#define HIDDEN 16
#define K_   8
#define ATT_CH 4
#define EPS_ 1e-5f

// ---------------- device scratch (zero-init at module load; finalize re-zeros) ----------------
__device__ float g_sumc[B_ * C_];   // per (b,c): sum over s of x
__device__ float g_num [B_ * C_];   // per (b,c): sum over s of x*exp(l_s)
__device__ float g_D   [B_];        // per b: sum over s of exp(l_s)
__device__ float g_summ[B_];        // per b: sum over s of max_c x

// ---------------- kernel 1: single streaming pass over x ----------------
__global__ __launch_bounds__(256) void pass1(const float* __restrict__ x,
                                             const float* __restrict__ w_mask,
                                             const float* __restrict__ b_mask) {
    __shared__ __align__(16) float sx[C_][TILE];    // 32 KB
    __shared__ float sw[C_];
    __shared__ float aux_l[8][TILE];
    __shared__ float aux_m[8][TILE];
    __shared__ float se[TILE];

    const int t    = threadIdx.x;    // 0..255
    const int w    = t >> 5;
    const int lane = t & 31;
    const int b    = blockIdx.y;
    const int tile0 = blockIdx.x * SUBT;

    sw[t] = w_mask[t];
    const float bm = b_mask[0];

    float svs = 0.f, sves = 0.f;     // per-thread channel (c = t) accumulators
    float accD = 0.f, accM = 0.f;    // valid in t==0 only

    const float4* xb_base = reinterpret_cast<const float4*>(x)
                          + (size_t)b * C_ * (HW_ / 4);

    for (int sub = 0; sub < SUBT; ++sub) {
        const int tile = tile0 + sub;
        const float4* xb = xb_base + (size_t)tile * (TILE / 4);

        // ---- coalesced tile load: each warp loads 4 rows/iter (lanes 0-7 one row)
        #pragma unroll
        for (int it = 0; it < 8; ++it) {
            int c = it * 32 + w * 4 + (lane >> 3);
            int i = lane & 7;
            float4 v = xb[(size_t)c * (HW_ / 4) + i];
            *reinterpret_cast<float4*>(&sx[c][i * 4]) = v;
        }
        __syncthreads();

        // ---- per-position partials over channels (warp = channel part, lane = position)
        {
            float lp = 0.f, mp = -1e30f;
            #pragma unroll 8
            for (int cc = 0; cc < 32; ++cc) {
                int c = w * 32 + cc;
                float v = sx[c][lane];
                lp = fmaf(v, sw[c], lp);
                mp = fmaxf(mp, v);
            }
            aux_l[w][lane] = lp; aux_m[w][lane] = mp;
        }
        __syncthreads();

        // ---- combine per-position partials; accumulate block scalars in registers
        if (t < TILE) {
            float l = bm, m = -1e30f;
            #pragma unroll
            for (int p = 0; p < 8; ++p) {
                l += aux_l[p][t];
                m  = fmaxf(m, aux_m[p][t]);
            }
            float e = __expf(l);     // unnormalized softmax weight (logits O(3))
            se[t] = e;
            #pragma unroll
            for (int off = 16; off > 0; off >>= 1) {
                e += __shfl_down_sync(0xffffffffu, e, off);
                m += __shfl_down_sync(0xffffffffu, m, off);
            }
            if (t == 0) { accD += e; accM += m; }
        }
        __syncthreads();

        // ---- per-channel accumulation (thread t owns channel t), rotated -> conflict-free
        {
            const int c = t;
            #pragma unroll 8
            for (int q = 0; q < TILE; ++q) {
                int jj = (q + c) & (TILE - 1);
                float v = sx[c][jj];
                svs += v;
                sves = fmaf(v, se[jj], sves);
            }
        }
        __syncthreads();   // sx/se reused next iteration
    }

    atomicAdd(&g_sumc[b * C_ + t], svs);
    atomicAdd(&g_num [b * C_ + t], sves);
    if (t == 0) { atomicAdd(&g_D[b], accD); atomicAdd(&g_summ[b], accM); }
}

// ---------------- kernel 2: per-batch finalizer (warp-cooperative matvecs) ----------------
__global__ __launch_bounds__(256) void finalize(
        const float* __restrict__ w_cm1, const float* __restrict__ b_cm1,
        const float* __restrict__ ln_w,  const float* __restrict__ ln_b,
        const float* __restrict__ w_cm2, const float* __restrict__ b_cm2,
        const float* __restrict__ w_net1, const float* __restrict__ w_net2,
        const float* __restrict__ w_fc,
        const float* __restrict__ bn_w,  const float* __restrict__ bn_b,
        const float* __restrict__ bn_mean, const float* __restrict__ bn_var,
        const float* __restrict__ w_kfc,
        float* __restrict__ out) {
    __shared__ __align__(16) float ctx[C_];
    __shared__ __align__(16) float bc[C_];
    __shared__ __align__(16) float tv[PLANES];
    __shared__ __align__(16) float tg[PLANES];
    __shared__ __align__(16) float sout[C_];
    __shared__ float red_s[4], red_q[4], red_a[8];
    __shared__ float hid[HIDDEN], o8[K_], kar[ATT_CH], fv[K_];
    __shared__ float sh_mval;

    const int t = threadIdx.x;       // 0..255
    const int b = blockIdx.x;
    const int lane = t & 31, wp = t >> 5;

    const float invD = 1.f / g_D[b];
    if (t == 0) sh_mval = g_summ[b] * (1.f / (float)HW_);

    ctx[t] = g_num [b * C_ + t] * invD;
    bc[t]  = g_sumc[b * C_ + t] * (1.f / (float)HW_);

    // aval = mean over channels of bc
    {
        float s = bc[t];
        #pragma unroll
        for (int off = 16; off > 0; off >>= 1) s += __shfl_down_sync(0xffffffffu, s, off);
        if (lane == 0) red_a[wp] = s;
    }
    __syncthreads();

    // re-zero scratch for next graph replay
    g_num [b * C_ + t] = 0.f;
    g_sumc[b * C_ + t] = 0.f;
    if (t == 0) { g_D[b] = 0.f; g_summ[b] = 0.f; }

    const float aval = (red_a[0] + red_a[1] + red_a[2] + red_a[3] +
                        red_a[4] + red_a[5] + red_a[6] + red_a[7]) * (1.f / (float)C_);
    const float mv = sh_mval;

    // ---- conv1 (128x256): warp wp computes planes wp*16 .. wp*16+15, coalesced rows
    {
        const float4* ctx4 = reinterpret_cast<const float4*>(ctx);
        const float4 c0 = ctx4[lane];
        const float4 c1 = ctx4[lane + 32];
        #pragma unroll 4
        for (int i = 0; i < 16; ++i) {
            int p = wp * 16 + i;
            const float4* w4 = reinterpret_cast<const float4*>(w_cm1 + p * C_);
            float4 a0 = w4[lane];
            float4 a1 = w4[lane + 32];
            float pr = a0.x * c0.x + a0.y * c0.y + a0.z * c0.z + a0.w * c0.w
                     + a1.x * c1.x + a1.y * c1.y + a1.z * c1.z + a1.w * c1.w;
            #pragma unroll
            for (int off = 16; off > 0; off >>= 1)
                pr += __shfl_down_sync(0xffffffffu, pr, off);
            if (lane == 0) tv[p] = pr + b_cm1[p];
        }
    }
    __syncthreads();

    // ---- LayerNorm over 128 planes + exact GELU
    {
        float tvv = (t < PLANES) ? tv[t] : 0.f;
        float s1 = tvv, s2 = tvv * tvv;
        #pragma unroll
        for (int off = 16; off > 0; off >>= 1) {
            s1 += __shfl_down_sync(0xffffffffu, s1, off);
            s2 += __shfl_down_sync(0xffffffffu, s2, off);
        }
        if (t < PLANES && lane == 0) { red_s[wp] = s1; red_q[wp] = s2; }
        __syncthreads();
        if (t < PLANES) {
            float S  = red_s[0] + red_s[1] + red_s[2] + red_s[3];
            float SQ = red_q[0] + red_q[1] + red_q[2] + red_q[3];
            float mu  = S * (1.f / PLANES);
            float var = SQ * (1.f / PLANES) - mu * mu;
            float tn = (tvv - mu) * rsqrtf(var + EPS_) * ln_w[t] + ln_b[t];
            tg[t] = 0.5f * tn * (1.f + erff(tn * 0.70710678118654752f));
        }
    }
    __syncthreads();

    // ---- conv2 (256x128): warp wp computes channels wp*32 .. wp*32+31
    {
        const float4* tg4 = reinterpret_cast<const float4*>(tg);
        const float4 g0 = tg4[lane];
        #pragma unroll 4
        for (int i = 0; i < 32; ++i) {
            int ch = wp * 32 + i;
            const float4* w4 = reinterpret_cast<const float4*>(w_cm2 + ch * PLANES);
            float4 a0 = w4[lane];
            float pr = a0.x * g0.x + a0.y * g0.y + a0.z * g0.z + a0.w * g0.w;
            #pragma unroll
            for (int off = 16; off > 0; off >>= 1)
                pr += __shfl_down_sync(0xffffffffu, pr, off);
            if (lane == 0)
                sout[ch] = bc[ch] + pr + b_cm2[ch] + ((ch & 1) ? mv : aval);
        }
    }
    __syncthreads();

    // ---- net1 (16x256): warp wp computes hidden wp*2, wp*2+1
    {
        const float4* so4 = reinterpret_cast<const float4*>(sout);
        const float4 s0 = so4[lane];
        const float4 s1v = so4[lane + 32];
        #pragma unroll
        for (int j = 0; j < 2; ++j) {
            int hh = wp * 2 + j;
            const float4* w4 = reinterpret_cast<const float4*>(w_net1 + hh * C_);
            float4 a0 = w4[lane];
            float4 a1 = w4[lane + 32];
            float pr = a0.x * s0.x + a0.y * s0.y + a0.z * s0.z + a0.w * s0.w
                     + a1.x * s1v.x + a1.y * s1v.y + a1.z * s1v.z + a1.w * s1v.w;
            #pragma unroll
            for (int off = 16; off > 0; off >>= 1)
                pr += __shfl_down_sync(0xffffffffu, pr, off);
            if (lane == 0) hid[hh] = fmaxf(pr, 0.f);
        }
    }
    __syncthreads();

    // ---- tiny tail: net2, kernel-attention, softmax
    if (t < K_) {
        float o = 0.f;
        #pragma unroll
        for (int q = 0; q < HIDDEN; ++q) o = fmaf(hid[q], w_net2[t * HIDDEN + q], o);
        o8[t] = o;
    }
    __syncthreads();
    if (t < ATT_CH) {
        float ka = 0.f;
        #pragma unroll
        for (int k = 0; k < K_; ++k) ka = fmaf(o8[k], w_fc[t * K_ + k], ka);
        ka = (ka - bn_mean[t]) * rsqrtf(bn_var[t] + EPS_) * bn_w[t] + bn_b[t];
        kar[t] = fmaxf(ka, 0.f);
    }
    __syncthreads();
    if (t < K_) {
        float kk = 0.f;
        #pragma unroll
        for (int q = 0; q < ATT_CH; ++q) kk = fmaf(kar[q], w_kfc[t * ATT_CH + q], kk);
        float ker = 1.f / (1.f + __expf(-kk));
        fv[t] = o8[t] * ker * (1.f / 30.f);
    }
    __syncthreads();
    if (t == 0) {
        float mx = -1e30f;
        #pragma unroll
        for (int k = 0; k < K_; ++k) mx = fmaxf(mx, fv[k]);
        float e[K_], s = 0.f;
        #pragma unroll
        for (int k = 0; k < K_; ++k) { e[k] = __expf(fv[k] - mx); s += e[k]; }
        float inv = 1.f / s;
        #pragma unroll
        for (int k = 0; k < K_; ++k) out[b * K_ + k] = e[k] * inv;
    }
}

// ---------------- launch ----------------
extern "C" void kernel_launch(void* const* d_in, const int* in_sizes, int n_in,
                              void* d_out, int out_size) {
    const float* x      = (const float*)d_in[0];
    const float* w_mask = (const float*)d_in[1];
    const float* b_mask = (const float*)d_in[2];
    const float* w_cm1  = (const float*)d_in[3];
    const float* b_cm1  = (const float*)d_in[4];
    const float* ln_w   = (const float*)d_in[5];
    const float* ln_b   = (const float*)d_in[6];
    const float* w_cm2  = (const float*)d_in[7];
    const float* b_cm2  = (const float*)d_in[8];
    const float* w_net1 = (const float*)d_in[9];
    const float* w_net2 = (const float*)d_in[10];
    const float* w_fc   = (const float*)d_in[11];
    const float* bn_w   = (const float*)d_in[12];
    const float* bn_b   = (const float*)d_in[13];
    const float* bn_mean= (const float*)d_in[14];
    const float* bn_var = (const float*)d_in[15];
    const float* w_kfc  = (const float*)d_in[16];
    float* out = (float*)d_out;

    pass1<<<dim3(NBLK, B_), 256>>>(x, w_mask, b_mask);
    finalize<<<B_, 256>>>(w_cm1, b_cm1, ln_w, ln_b, w_cm2, b_cm2,
                          w_net1, w_net2, w_fc, bn_w, bn_b, bn_mean, bn_var,
                          w_kfc, out);
}

// round 4
// speedup vs baseline: 1.6752x; 1.2692x over previous
#include <cuda_runtime.h>
#include <math.h>

// ---------------- problem constants ----------------
#define B_   64
#define C_   256
#define HW_  4096            // 64*64
#define TILE 32              // spatial positions per tile
#define SUBT 8               // tiles per CTA
#define NBLK 16              // CTAs per batch  (16*8*32 = 4096)
#define PLANES 128
#define HIDDEN 16
#define K_   8
#define ATT_CH 4
#define EPS_ 1e-5f

// ---------------- device scratch (zero-init at load; last CTA re-zeros) ----------------
__device__ float    g_sumc[B_ * C_];
__device__ float    g_num [B_ * C_];
__device__ float    g_D   [B_];
__device__ float    g_summ[B_];
__device__ unsigned g_cnt [B_];

// ---------------- dynamic smem layout (floats) ----------------
#define SX0  0                 // 8192 f (32 KB) tile buffer 0
#define SX1  8192              // 8192 f        tile buffer 1
#define AL   16384             // 1024 f  logit partials [32 part][32 pos]
#define AM   17408             // 1024 f  max partials
#define SE   18432             // 32 f    exp weights
#define SMEM_FLOATS (18432 + 64)
#define SMEM_BYTES  (SMEM_FLOATS * 4)    // 73984 B -> 3 CTAs/SM

// ---------------- cp.async helpers ----------------
__device__ __forceinline__ void cp16(float* s, const float4* g) {
    unsigned sa = (unsigned)__cvta_generic_to_shared(s);
    asm volatile("cp.async.cg.shared.global [%0], [%1], 16;\n" :: "r"(sa), "l"(g));
}
#define CP_COMMIT()  asm volatile("cp.async.commit_group;\n")
#define CP_WAIT(n)   asm volatile("cp.async.wait_group %0;\n" :: "n"(n))

__global__ __launch_bounds__(256) void fused(
        const float* __restrict__ x,
        const float* __restrict__ w_mask, const float* __restrict__ b_mask,
        const float* __restrict__ w_cm1, const float* __restrict__ b_cm1,
        const float* __restrict__ ln_w,  const float* __restrict__ ln_b,
        const float* __restrict__ w_cm2, const float* __restrict__ b_cm2,
        const float* __restrict__ w_net1, const float* __restrict__ w_net2,
        const float* __restrict__ w_fc,
        const float* __restrict__ bn_w,  const float* __restrict__ bn_b,
        const float* __restrict__ bn_mean, const float* __restrict__ bn_var,
        const float* __restrict__ w_kfc,
        float* __restrict__ out) {
    extern __shared__ __align__(16) float sm[];
    __shared__ int s_last;

    const int t    = threadIdx.x;    // 0..255
    const int lane = t & 31;
    const int wp   = t >> 5;
    const int b    = blockIdx.x >> 4;         // batch
    const int blk  = blockIdx.x & (NBLK - 1); // block within batch
    const int tile0 = blk * SUBT;

    const int cg = t >> 3;           // channel group 0..31 (8 channels each)
    const int q  = t & 7;            // position quad 0..7

    // hoisted mask weights for this thread's 8 channels
    float4 wv0 = *reinterpret_cast<const float4*>(w_mask + cg * 8);
    float4 wv1 = *reinterpret_cast<const float4*>(w_mask + cg * 8 + 4);
    const float wreg[8] = {wv0.x, wv0.y, wv0.z, wv0.w, wv1.x, wv1.y, wv1.z, wv1.w};
    const float bm = b_mask[0];

    const float4* xb = reinterpret_cast<const float4*>(x) + (size_t)b * C_ * (HW_ / 4);

    // per-thread accumulators across tiles
    float4 sv  = make_float4(0.f, 0.f, 0.f, 0.f);   // channel-sum  (channel = t)
    float4 sve = make_float4(0.f, 0.f, 0.f, 0.f);   // weighted sum
    float run_e = 0.f, run_m = 0.f;                 // valid t<32

    // ---- prefetch tile 0 ----
    {
        float* dst = sm + SX0;
        const float4* src = xb + (size_t)tile0 * 8;
        #pragma unroll
        for (int it = 0; it < 8; ++it) {
            int c = it * 32 + cg;
            cp16(dst + c * 32 + q * 4, src + (size_t)c * (HW_ / 4) + q);
        }
        CP_COMMIT();
    }

    for (int sub = 0; sub < SUBT; ++sub) {
        float* cur = sm + ((sub & 1) ? SX1 : SX0);
        if (sub + 1 < SUBT) {
            float* dst = sm + (((sub + 1) & 1) ? SX1 : SX0);
            const float4* src = xb + (size_t)(tile0 + sub + 1) * 8;
            #pragma unroll
            for (int it = 0; it < 8; ++it) {
                int c = it * 32 + cg;
                cp16(dst + c * 32 + q * 4, src + (size_t)c * (HW_ / 4) + q);
            }
            CP_COMMIT();
            CP_WAIT(1);
        } else {
            CP_WAIT(0);
        }
        __syncthreads();

        // ---- phase2: logit & max partials (8 channels x 4 positions per thread) ----
        {
            float4 lp = make_float4(0.f, 0.f, 0.f, 0.f);
            float4 mp = make_float4(-1e30f, -1e30f, -1e30f, -1e30f);
            #pragma unroll
            for (int i = 0; i < 8; ++i) {
                const float4 v = *reinterpret_cast<const float4*>(cur + (cg * 8 + i) * 32 + q * 4);
                const float wc = wreg[i];
                lp.x = fmaf(v.x, wc, lp.x); lp.y = fmaf(v.y, wc, lp.y);
                lp.z = fmaf(v.z, wc, lp.z); lp.w = fmaf(v.w, wc, lp.w);
                mp.x = fmaxf(mp.x, v.x);    mp.y = fmaxf(mp.y, v.y);
                mp.z = fmaxf(mp.z, v.z);    mp.w = fmaxf(mp.w, v.w);
            }
            *reinterpret_cast<float4*>(sm + AL + cg * 32 + q * 4) = lp;
            *reinterpret_cast<float4*>(sm + AM + cg * 32 + q * 4) = mp;
        }
        __syncthreads();

        // ---- combine: threads 0..31, position t; bank-conflict-free (bank = t) ----
        if (t < TILE) {
            float l = bm, m = -1e30f;
            #pragma unroll
            for (int p = 0; p < 32; ++p) {
                l += sm[AL + p * 32 + t];
                m  = fmaxf(m, sm[AM + p * 32 + t]);
            }
            float e = __expf(l);          // unnormalized softmax weight (logits O(3))
            sm[SE + t] = e;
            run_e += e;
            run_m += m;
        }
        __syncthreads();

        // ---- phase3: per-channel accumulation, rotated quads (conflict-free) ----
        {
            const int rot = t & 7;
            #pragma unroll
            for (int q2 = 0; q2 < 8; ++q2) {
                int jj = (q2 + rot) & 7;
                const float4 v = *reinterpret_cast<const float4*>(cur + t * 32 + jj * 4);
                const float4 e = *reinterpret_cast<const float4*>(sm + SE + jj * 4);
                sv.x += v.x; sv.y += v.y; sv.z += v.z; sv.w += v.w;
                sve.x = fmaf(v.x, e.x, sve.x); sve.y = fmaf(v.y, e.y, sve.y);
                sve.z = fmaf(v.z, e.z, sve.z); sve.w = fmaf(v.w, e.w, sve.w);
            }
        }
        __syncthreads();   // buffer reuse barrier
    }

    // ---- global accumulation ----
    atomicAdd(&g_sumc[b * C_ + t], (sv.x + sv.y) + (sv.z + sv.w));
    atomicAdd(&g_num [b * C_ + t], (sve.x + sve.y) + (sve.z + sve.w));
    if (t < TILE) {
        #pragma unroll
        for (int off = 16; off > 0; off >>= 1) {
            run_e += __shfl_down_sync(0xffffffffu, run_e, off);
            run_m += __shfl_down_sync(0xffffffffu, run_m, off);
        }
        if (t == 0) { atomicAdd(&g_D[b], run_e); atomicAdd(&g_summ[b], run_m); }
    }
    __threadfence();
    __syncthreads();
    if (t == 0) {
        unsigned old = atomicAdd(&g_cnt[b], 1u);
        s_last = (old == NBLK - 1);
    }
    __syncthreads();
    if (!s_last) return;

    // ================= finalize (last CTA of this batch) =================
    float* ctx   = sm;            // 256
    float* bcv   = sm + 256;      // 256
    float* tvs   = sm + 512;      // 128
    float* tg    = sm + 640;      // 128
    float* sout  = sm + 768;      // 256
    float* red_s = sm + 1024;     // 4
    float* red_q = sm + 1028;     // 4
    float* red_a = sm + 1032;     // 8
    float* hid   = sm + 1040;     // 16
    float* o8    = sm + 1056;     // 8
    float* kar   = sm + 1064;     // 4
    float* fvv   = sm + 1072;     // 8
    float* shm   = sm + 1080;     // 1

    const float Dv    = __ldcg(&g_D[b]);
    const float summv = __ldcg(&g_summ[b]);
    const float numv  = __ldcg(&g_num [b * C_ + t]);
    const float sumcv = __ldcg(&g_sumc[b * C_ + t]);

    // re-zero scratch for next graph replay (this CTA is the only reader)
    g_num [b * C_ + t] = 0.f;
    g_sumc[b * C_ + t] = 0.f;
    if (t == 0) { g_D[b] = 0.f; g_summ[b] = 0.f; g_cnt[b] = 0u; shm[0] = summv * (1.f / (float)HW_); }

    ctx[t] = numv  * (1.f / Dv);
    bcv[t] = sumcv * (1.f / (float)HW_);
    {
        float s = sumcv * (1.f / (float)HW_);
        #pragma unroll
        for (int off = 16; off > 0; off >>= 1) s += __shfl_down_sync(0xffffffffu, s, off);
        if (lane == 0) red_a[wp] = s;
    }
    __syncthreads();

    const float aval = (red_a[0] + red_a[1] + red_a[2] + red_a[3] +
                        red_a[4] + red_a[5] + red_a[6] + red_a[7]) * (1.f / (float)C_);
    const float mv = shm[0];

    // conv1 (128x256): warp wp -> planes wp*16..+15
    {
        const float4* ctx4 = reinterpret_cast<const float4*>(ctx);
        const float4 c0 = ctx4[lane];
        const float4 c1 = ctx4[lane + 32];
        #pragma unroll 4
        for (int i = 0; i < 16; ++i) {
            int p = wp * 16 + i;
            const float4* w4 = reinterpret_cast<const float4*>(w_cm1 + p * C_);
            float4 a0 = w4[lane];
            float4 a1 = w4[lane + 32];
            float pr = a0.x * c0.x + a0.y * c0.y + a0.z * c0.z + a0.w * c0.w
                     + a1.x * c1.x + a1.y * c1.y + a1.z * c1.z + a1.w * c1.w;
            #pragma unroll
            for (int off = 16; off > 0; off >>= 1)
                pr += __shfl_down_sync(0xffffffffu, pr, off);
            if (lane == 0) tvs[p] = pr + b_cm1[p];
        }
    }
    __syncthreads();

    // LayerNorm(128) + exact GELU
    {
        float tvv = (t < PLANES) ? tvs[t] : 0.f;
        float s1 = tvv, s2 = tvv * tvv;
        #pragma unroll
        for (int off = 16; off > 0; off >>= 1) {
            s1 += __shfl_down_sync(0xffffffffu, s1, off);
            s2 += __shfl_down_sync(0xffffffffu, s2, off);
        }
        if (t < PLANES && lane == 0) { red_s[wp] = s1; red_q[wp] = s2; }
        __syncthreads();
        if (t < PLANES) {
            float S  = red_s[0] + red_s[1] + red_s[2] + red_s[3];
            float SQ = red_q[0] + red_q[1] + red_q[2] + red_q[3];
            float mu  = S * (1.f / PLANES);
            float var = SQ * (1.f / PLANES) - mu * mu;
            float tn = (tvv - mu) * rsqrtf(var + EPS_) * ln_w[t] + ln_b[t];
            tg[t] = 0.5f * tn * (1.f + erff(tn * 0.70710678118654752f));
        }
    }
    __syncthreads();

    // conv2 (256x128): warp wp -> channels wp*32..+31
    {
        const float4* tg4 = reinterpret_cast<const float4*>(tg);
        const float4 g0 = tg4[lane];
        #pragma unroll 4
        for (int i = 0; i < 32; ++i) {
            int ch = wp * 32 + i;
            const float4* w4 = reinterpret_cast<const float4*>(w_cm2 + ch * PLANES);
            float4 a0 = w4[lane];
            float pr = a0.x * g0.x + a0.y * g0.y + a0.z * g0.z + a0.w * g0.w;
            #pragma unroll
            for (int off = 16; off > 0; off >>= 1)
                pr += __shfl_down_sync(0xffffffffu, pr, off);
            if (lane == 0)
                sout[ch] = bcv[ch] + pr + b_cm2[ch] + ((ch & 1) ? mv : aval);
        }
    }
    __syncthreads();

    // net1 (16x256): warp wp -> hidden wp*2, wp*2+1
    {
        const float4* so4 = reinterpret_cast<const float4*>(sout);
        const float4 s0 = so4[lane];
        const float4 s1v = so4[lane + 32];
        #pragma unroll
        for (int j = 0; j < 2; ++j) {
            int hh = wp * 2 + j;
            const float4* w4 = reinterpret_cast<const float4*>(w_net1 + hh * C_);
            float4 a0 = w4[lane];
            float4 a1 = w4[lane + 32];
            float pr = a0.x * s0.x + a0.y * s0.y + a0.z * s0.z + a0.w * s0.w
                     + a1.x * s1v.x + a1.y * s1v.y + a1.z * s1v.z + a1.w * s1v.w;
            #pragma unroll
            for (int off = 16; off > 0; off >>= 1)
                pr += __shfl_down_sync(0xffffffffu, pr, off);
            if (lane == 0) hid[hh] = fmaxf(pr, 0.f);
        }
    }
    __syncthreads();

    if (t < K_) {
        float o = 0.f;
        #pragma unroll
        for (int q2 = 0; q2 < HIDDEN; ++q2) o = fmaf(hid[q2], w_net2[t * HIDDEN + q2], o);
        o8[t] = o;
    }
    __syncthreads();
    if (t < ATT_CH) {
        float ka = 0.f;
        #pragma unroll
        for (int k = 0; k < K_; ++k) ka = fmaf(o8[k], w_fc[t * K_ + k], ka);
        ka = (ka - bn_mean[t]) * rsqrtf(bn_var[t] + EPS_) * bn_w[t] + bn_b[t];
        kar[t] = fmaxf(ka, 0.f);
    }
    __syncthreads();
    if (t < K_) {
        float kk = 0.f;
        #pragma unroll
        for (int q2 = 0; q2 < ATT_CH; ++q2) kk = fmaf(kar[q2], w_kfc[t * ATT_CH + q2], kk);
        float ker = 1.f / (1.f + __expf(-kk));
        fvv[t] = o8[t] * ker * (1.f / 30.f);
    }
    __syncthreads();
    if (t == 0) {
        float mx = -1e30f;
        #pragma unroll
        for (int k = 0; k < K_; ++k) mx = fmaxf(mx, fvv[k]);
        float e[K_], s = 0.f;
        #pragma unroll
        for (int k = 0; k < K_; ++k) { e[k] = __expf(fvv[k] - mx); s += e[k]; }
        float inv = 1.f / s;
        #pragma unroll
        for (int k = 0; k < K_; ++k) out[b * K_ + k] = e[k] * inv;
    }
}

// ---------------- launch ----------------
extern "C" void kernel_launch(void* const* d_in, const int* in_sizes, int n_in,
                              void* d_out, int out_size) {
    const float* x      = (const float*)d_in[0];
    const float* w_mask = (const float*)d_in[1];
    const float* b_mask = (const float*)d_in[2];
    const float* w_cm1  = (const float*)d_in[3];
    const float* b_cm1  = (const float*)d_in[4];
    const float* ln_w   = (const float*)d_in[5];
    const float* ln_b   = (const float*)d_in[6];
    const float* w_cm2  = (const float*)d_in[7];
    const float* b_cm2  = (const float*)d_in[8];
    const float* w_net1 = (const float*)d_in[9];
    const float* w_net2 = (const float*)d_in[10];
    const float* w_fc   = (const float*)d_in[11];
    const float* bn_w   = (const float*)d_in[12];
    const float* bn_b   = (const float*)d_in[13];
    const float* bn_mean= (const float*)d_in[14];
    const float* bn_var = (const float*)d_in[15];
    const float* w_kfc  = (const float*)d_in[16];
    float* out = (float*)d_out;

    static bool configured = false;
    if (!configured) {
        cudaFuncSetAttribute(fused, cudaFuncAttributeMaxDynamicSharedMemorySize, SMEM_BYTES);
        configured = true;
    }
    fused<<<B_ * NBLK, 256, SMEM_BYTES>>>(x, w_mask, b_mask,
                          w_cm1, b_cm1, ln_w, ln_b, w_cm2, b_cm2,
                          w_net1, w_net2, w_fc, bn_w, bn_b, bn_mean, bn_var,
                          w_kfc, out);
}